// round 15
// baseline (speedup 1.0000x reference)
#include <cuda_runtime.h>
#include <cuda_bf16.h>
#include <cuda_fp16.h>
#include <math.h>
#include <stdint.h>

#define SS 128
#define BB 128
#define VV 10000
#define HH 512
#define EE 512
#define KDIM 512

#define NB_N 79                          // ceil(10000/128)
#define N_TILES (SS * NB_N)              // 10112 logits tiles

// ---------------- scratch (device globals: no allocations allowed) ----------
__device__ float g_P[VV * HH];
__device__ unsigned int g_sync4[128];    // 4 batch-group barriers, 128B apart
__device__ unsigned int g_ticket;        // logits tile allocator
__device__ __nv_bfloat16 g_h0bh[2][BB * HH], g_h0bl[2][BB * HH];
__device__ __nv_bfloat16 g_h1bh[2][BB * HH], g_h1bl[2][BB * HH];
__device__ __half g_T16[SS * BB * HH];
__device__ __half g_W16[VV * HH];
__device__ __half g_E16h[VV * EE];
__device__ __half g_E16l[VV * EE];
__device__ __half g_X16[HH * EE];

// ============================ helpers ========================================
__device__ __forceinline__ uint32_t smem_u32(const void* p) {
    uint32_t a;
    asm("{ .reg .u64 t; cvta.to.shared.u64 t, %1; cvt.u32.u64 %0, t; }"
        : "=r"(a) : "l"(p));
    return a;
}

__device__ __forceinline__ void ldm_x4(uint32_t addr, uint32_t r[4]) {
    asm volatile("ldmatrix.sync.aligned.m8n8.x4.shared.b16 {%0,%1,%2,%3}, [%4];"
                 : "=r"(r[0]), "=r"(r[1]), "=r"(r[2]), "=r"(r[3]) : "r"(addr));
}

__device__ __forceinline__ void mma_bf16(float c[4], const uint32_t a[4],
                                         uint32_t b0, uint32_t b1) {
    asm volatile(
        "mma.sync.aligned.m16n8k16.row.col.f32.bf16.bf16.f32 "
        "{%0,%1,%2,%3}, {%4,%5,%6,%7}, {%8,%9}, {%0,%1,%2,%3};"
        : "+f"(c[0]), "+f"(c[1]), "+f"(c[2]), "+f"(c[3])
        : "r"(a[0]), "r"(a[1]), "r"(a[2]), "r"(a[3]), "r"(b0), "r"(b1));
}

__device__ __forceinline__ void mma_fp16(float c[4], const uint32_t a[4],
                                         uint32_t b0, uint32_t b1) {
    asm volatile(
        "mma.sync.aligned.m16n8k16.row.col.f32.f16.f16.f32 "
        "{%0,%1,%2,%3}, {%4,%5,%6,%7}, {%8,%9}, {%0,%1,%2,%3};"
        : "+f"(c[0]), "+f"(c[1]), "+f"(c[2]), "+f"(c[3])
        : "r"(a[0]), "r"(a[1]), "r"(a[2]), "r"(a[3]), "r"(b0), "r"(b1));
}

#define BK 32
#define ROWB 80
#define TILE_SB (128 * ROWB)
#define KT_N (KDIM / BK)               // 16

// =================== fp16 2-pass HMMA GEMM (P matrix) ========================
#define F16_STAGE (3 * TILE_SB)          // 30720
#define F16_SMEM (2 * F16_STAGE)         // 61440

__global__ __launch_bounds__(256, 2)
void gemm_fp16(const __half* __restrict__ Ahi,
               const __half* __restrict__ Alo,
               const __half* __restrict__ Bh,
               int M, int N, float* __restrict__ C, int ldc,
               const float* __restrict__ bias) {
    extern __shared__ char smem[];
    const uint32_t sb = smem_u32(smem);
    const int tid = threadIdx.x;
    const int wid = tid >> 5, lid = tid & 31;
    const int wm = wid & 3, wn = wid >> 2;
    const int nb = blockIdx.x, mb = blockIdx.y;

    const __half* __restrict__ srcs[3] = {Ahi, Alo, Bh};

    float acc[2][8][4];
#pragma unroll
    for (int i = 0; i < 2; i++)
#pragma unroll
        for (int j = 0; j < 8; j++)
#pragma unroll
            for (int q = 0; q < 4; q++) acc[i][j][q] = 0.0f;

    auto load_stage = [&](int st, int kt) {
#pragma unroll
        for (int t = 0; t < 3; t++) {
#pragma unroll
            for (int i = 0; i < 2; i++) {
                const int idx = tid + i * 256;
                const int row = idx >> 2, ch = idx & 3;
                const long long grow =
                    (t < 2) ? (long long)mb * 128 + row : (long long)nb * 128 + row;
                const bool ok = (t < 2) ? (grow < M) : (grow < N);
                const __half* src = srcs[t] + grow * KDIM + kt * BK + ch * 8;
                const uint32_t dst = sb + st * F16_STAGE + t * TILE_SB + row * ROWB + ch * 16;
                const int sz = ok ? 16 : 0;
                asm volatile("cp.async.cg.shared.global [%0], [%1], 16, %2;"
                             :: "r"(dst), "l"(src), "r"(sz) : "memory");
            }
        }
        asm volatile("cp.async.commit_group;" ::: "memory");
    };

    const int lr = lid & 15;
    const int lc = lid >> 4;

    load_stage(0, 0);

    for (int kt = 0; kt < KT_N; kt++) {
        const int st = kt & 1;
        if (kt + 1 < KT_N) {
            load_stage(st ^ 1, kt + 1);
            asm volatile("cp.async.wait_group 1;" ::: "memory");
        } else {
            asm volatile("cp.async.wait_group 0;" ::: "memory");
        }
        __syncthreads();

        const uint32_t stg = sb + st * F16_STAGE;
        const uint32_t aBaseHi = stg + 0 * TILE_SB;
        const uint32_t aBaseLo = stg + 1 * TILE_SB;
        const uint32_t bBase = stg + 2 * TILE_SB;

#pragma unroll
        for (int k16 = 0; k16 < 2; k16++) {
            const uint32_t koff = k16 * 32 + lc * 16;

            uint32_t ahi[2][4], alo[2][4];
#pragma unroll
            for (int mf = 0; mf < 2; mf++) {
                const uint32_t roff = (uint32_t)(wm * 32 + mf * 16 + lr) * ROWB + koff;
                ldm_x4(aBaseHi + roff, ahi[mf]);
                ldm_x4(aBaseLo + roff, alo[mf]);
            }
#pragma unroll
            for (int reg = 0; reg < 4; reg++) {
                const uint32_t roff = (uint32_t)(wn * 64 + reg * 16 + lr) * ROWB + koff;
                uint32_t bh[4];
                ldm_x4(bBase + roff, bh);
#pragma unroll
                for (int mf = 0; mf < 2; mf++) {
                    mma_fp16(acc[mf][reg * 2 + 0], ahi[mf], bh[0], bh[2]);
                    mma_fp16(acc[mf][reg * 2 + 0], alo[mf], bh[0], bh[2]);
                    mma_fp16(acc[mf][reg * 2 + 1], ahi[mf], bh[1], bh[3]);
                    mma_fp16(acc[mf][reg * 2 + 1], alo[mf], bh[1], bh[3]);
                }
            }
        }
        __syncthreads();
    }

    const int lr4 = lid >> 2;
    const int lc2 = (lid & 3) * 2;
#pragma unroll
    for (int mf = 0; mf < 2; mf++) {
#pragma unroll
        for (int nf = 0; nf < 8; nf++) {
            const int m = mb * 128 + wm * 32 + mf * 16 + lr4;
            const int n = nb * 128 + wn * 64 + nf * 8 + lc2;
            if (n >= N) continue;
            float b0 = 0.f, b1 = 0.f;
            if (bias) { b0 = bias[n]; b1 = bias[n + 1]; }
            if (m < M) {
                float2 v = make_float2(acc[mf][nf][0] + b0, acc[mf][nf][1] + b1);
                *reinterpret_cast<float2*>(C + (long long)m * ldc + n) = v;
            }
            if (m + 8 < M) {
                float2 v = make_float2(acc[mf][nf][2] + b0, acc[mf][nf][3] + b1);
                *reinterpret_cast<float2*>(C + (long long)(m + 8) * ldc + n) = v;
            }
        }
    }
}

// ========== fp16 single-pass logits tile (device fn, run inside rnn) ========
#define F161_STAGE (2 * TILE_SB)         // 20480
// uses first 2*F161_STAGE = 40960 B of the caller's dynamic smem

__device__ __noinline__ void logits_tile(uint32_t sb, int mb, int nb,
                                         float* __restrict__ C,
                                         const float* __restrict__ bias) {
    const int tid = threadIdx.x;
    const int wid = tid >> 5, lid = tid & 31;
    const int wm = wid & 3, wn = wid >> 2;
    const __half* __restrict__ A16 = g_T16;
    const __half* __restrict__ B16 = g_W16;

    float acc[2][8][4];
#pragma unroll
    for (int i = 0; i < 2; i++)
#pragma unroll
        for (int j = 0; j < 8; j++)
#pragma unroll
            for (int q = 0; q < 4; q++) acc[i][j][q] = 0.0f;

    auto load_stage = [&](int st, int kt) {
#pragma unroll
        for (int t = 0; t < 2; t++) {
#pragma unroll
            for (int i = 0; i < 2; i++) {
                const int idx = tid + i * 256;
                const int row = idx >> 2, ch = idx & 3;
                const long long grow =
                    (t == 0) ? (long long)mb * 128 + row : (long long)nb * 128 + row;
                const bool ok = (t == 0) || (grow < VV);
                const __half* src = (t == 0 ? A16 : B16) + grow * KDIM + kt * BK + ch * 8;
                const uint32_t dst = sb + st * F161_STAGE + t * TILE_SB + row * ROWB + ch * 16;
                const int sz = ok ? 16 : 0;
                asm volatile("cp.async.cg.shared.global [%0], [%1], 16, %2;"
                             :: "r"(dst), "l"(src), "r"(sz) : "memory");
            }
        }
        asm volatile("cp.async.commit_group;" ::: "memory");
    };

    const int lr = lid & 15;
    const int lc = lid >> 4;

    load_stage(0, 0);

    for (int kt = 0; kt < KT_N; kt++) {
        const int st = kt & 1;
        if (kt + 1 < KT_N) {
            load_stage(st ^ 1, kt + 1);
            asm volatile("cp.async.wait_group 1;" ::: "memory");
        } else {
            asm volatile("cp.async.wait_group 0;" ::: "memory");
        }
        __syncthreads();

        const uint32_t stg = sb + st * F161_STAGE;
        const uint32_t aBase = stg;
        const uint32_t bBase = stg + TILE_SB;

#pragma unroll
        for (int k16 = 0; k16 < 2; k16++) {
            const uint32_t koff = k16 * 32 + lc * 16;

            uint32_t af[2][4];
#pragma unroll
            for (int mf = 0; mf < 2; mf++) {
                const uint32_t roff = (uint32_t)(wm * 32 + mf * 16 + lr) * ROWB + koff;
                ldm_x4(aBase + roff, af[mf]);
            }
#pragma unroll
            for (int reg = 0; reg < 4; reg++) {
                const uint32_t roff = (uint32_t)(wn * 64 + reg * 16 + lr) * ROWB + koff;
                uint32_t bh[4];
                ldm_x4(bBase + roff, bh);
#pragma unroll
                for (int mf = 0; mf < 2; mf++) {
                    mma_fp16(acc[mf][reg * 2 + 0], af[mf], bh[0], bh[2]);
                    mma_fp16(acc[mf][reg * 2 + 1], af[mf], bh[1], bh[3]);
                }
            }
        }
        __syncthreads();
    }

    const int lr4 = lid >> 2;
    const int lc2 = (lid & 3) * 2;
#pragma unroll
    for (int mf = 0; mf < 2; mf++) {
#pragma unroll
        for (int nf = 0; nf < 8; nf++) {
            const int m = mb * 128 + wm * 32 + mf * 16 + lr4;
            const int n = nb * 128 + wn * 64 + nf * 8 + lc2;
            if (n >= VV) continue;
            const float b0 = bias[n], b1 = bias[n + 1];
            float2 v0 = make_float2(acc[mf][nf][0] + b0, acc[mf][nf][1] + b1);
            float2 v1 = make_float2(acc[mf][nf][2] + b0, acc[mf][nf][3] + b1);
            *reinterpret_cast<float2*>(C + (long long)m * VV + n) = v0;
            *reinterpret_cast<float2*>(C + (long long)(m + 8) * VV + n) = v1;
        }
    }
}

// =================== fused persistent kernel: recurrence + logits ===========
#define RNN_CTAS 148                      // 128 workers + 20 helpers
#define RNN_THR 256
#define WT16 16384
#define HT32 32768
#define OFF_W 0
#define OFF_H0 (6 * WT16)
#define OFF_H1 (OFF_H0 + 2 * HT32)
#define OFF_P (OFF_H1 + 2 * HT32)         // 229376
#define RNN_SMEM (OFF_P + 2048)           // 231424
#define OFF_R OFF_H0
#define REDSTR 17

__device__ __forceinline__ unsigned int ld_acq(const unsigned int* p) {
    unsigned int v;
    asm volatile("ld.acquire.gpu.global.u32 %0, [%1];" : "=r"(v) : "l"(p) : "memory");
    return v;
}

__global__ __launch_bounds__(RNN_THR, 1)
void rnn_fused(const int* __restrict__ inputs,
               const float* __restrict__ W0,
               const float* __restrict__ b0,
               const float* __restrict__ Wl,
               const float* __restrict__ bl,
               float* __restrict__ hfin,
               float* __restrict__ logits,
               const float* __restrict__ bout) {
    extern __shared__ char smc[];
    const uint32_t sbase = smem_u32(smc);
    float* const smf = reinterpret_cast<float*>(smc);
    const int tid = threadIdx.x;
    const int wid = tid >> 5, lid = tid & 31;

    if (blockIdx.x < 128) {
        // =================== recurrence worker ===================
        const int bg = blockIdx.x >> 5;
        const int cg = blockIdx.x & 31;
        const int cbase = cg * 16;

        for (int i = tid; i < 16 * 512; i += RNN_THR) {
            const int r = i >> 9, k = i & 511;
            const int gc = cbase + r;
            const uint32_t off = r * 1024 + (((k >> 3) ^ (r & 7)) << 4) + (k & 7) * 2;
            float v[3];
            v[0] = W0[gc * 1024 + k];
            v[1] = Wl[gc * 1024 + 512 + k];
            v[2] = Wl[gc * 1024 + k];
#pragma unroll
            for (int t = 0; t < 3; t++) {
                const __nv_bfloat16 hi = __float2bfloat16(v[t]);
                const __nv_bfloat16 lo = __float2bfloat16(v[t] - __bfloat162float(hi));
                char* base = smc + OFF_W + (2 * t) * WT16 + off;
                *reinterpret_cast<__nv_bfloat16*>(base) = hi;
                *reinterpret_cast<__nv_bfloat16*>(base + WT16) = lo;
            }
        }
        __syncthreads();

        const int mw = wid & 1;
        const int kw = wid >> 1;
        const int lr = lid & 15, lc = lid >> 4;

        const int ecoll = tid & 15, erow = tid >> 4;
        const int ecol = cbase + ecoll;
        const float b0c = b0[ecol], blc = bl[ecol];

        const int arow = mw * 16 + lr;
        const uint32_t aRowH0 = sbase + OFF_H0 + arow * 1024;
        const uint32_t aRowH1 = sbase + OFF_H1 + arow * 1024;
        const uint32_t bRow = sbase + OFF_W + lr * 1024;
        const int axor = arow & 7;
        const int bxor = lr & 7;
        const int c0 = kw * 16 + lc;

        unsigned int* const gbar = &g_sync4[bg * 32];

        auto stage_h = [&](uint32_t offBase, const __nv_bfloat16* hi,
                           const __nv_bfloat16* lo) {
#pragma unroll
            for (int j = 0; j < 16; j++) {
                const int idx = tid + j * 256;
                const int tile = idx >> 11;
                const int c = idx & 2047;
                const int row = c >> 6, ch = c & 63;
                const __nv_bfloat16* src =
                    (tile ? lo : hi) + (long long)(bg * 32 + row) * HH + ch * 8;
                const uint32_t dst = sbase + offBase + tile * HT32 + row * 1024 +
                                     ((ch ^ (row & 7)) << 4);
                asm volatile("cp.async.cg.shared.global [%0], [%1], 16;"
                             :: "r"(dst), "l"(src) : "memory");
            }
            asm volatile("cp.async.commit_group;" ::: "memory");
        };

        for (int p = 0; p <= SS; p++) {
            float acc0[2][4] = {{0, 0, 0, 0}, {0, 0, 0, 0}};
            float acc1[2][4] = {{0, 0, 0, 0}, {0, 0, 0, 0}};

            if (p < SS && tid < 128) {
                const int row = tid >> 2, ch = tid & 3;
                const int tok = __ldg(inputs + p * BB + bg * 32 + row);
                const float* src = g_P + (long long)tok * HH + cbase + ch * 4;
                const uint32_t dst = sbase + OFF_P + row * 64 + ch * 16;
                asm volatile("cp.async.cg.shared.global [%0], [%1], 16;"
                             :: "r"(dst), "l"(src) : "memory");
            }
            stage_h(OFF_H0, g_h0bh[(p + 1) & 1], g_h0bl[(p + 1) & 1]);
            stage_h(OFF_H1, g_h1bh[p & 1], g_h1bl[p & 1]);
            asm volatile("cp.async.wait_group 1;" ::: "memory");
            __syncthreads();

            // ---- pass A ----
#pragma unroll
            for (int i = 0; i < 8; i++) {
                const uint32_t sc = (uint32_t)((c0 + i * 2) ^ axor) << 4;
                const uint32_t wc = (uint32_t)((c0 + i * 2) ^ bxor) << 4;
                uint32_t ah[4], al[4], b0h[4], b0l[4], bxh[4], bxl[4];
                ldm_x4(aRowH0 + sc, ah);
                ldm_x4(aRowH0 + HT32 + sc, al);
                ldm_x4(bRow + 0 * WT16 + wc, b0h);
                ldm_x4(bRow + 1 * WT16 + wc, b0l);
                ldm_x4(bRow + 2 * WT16 + wc, bxh);
                ldm_x4(bRow + 3 * WT16 + wc, bxl);
                mma_bf16(acc0[0], ah, b0h[0], b0h[2]);
                mma_bf16(acc0[1], ah, b0h[1], b0h[3]);
                mma_bf16(acc0[0], ah, b0l[0], b0l[2]);
                mma_bf16(acc0[1], ah, b0l[1], b0l[3]);
                mma_bf16(acc0[0], al, b0h[0], b0h[2]);
                mma_bf16(acc0[1], al, b0h[1], b0h[3]);
                mma_bf16(acc1[0], ah, bxh[0], bxh[2]);
                mma_bf16(acc1[1], ah, bxh[1], bxh[3]);
                mma_bf16(acc1[0], ah, bxl[0], bxl[2]);
                mma_bf16(acc1[1], ah, bxl[1], bxl[3]);
                mma_bf16(acc1[0], al, bxh[0], bxh[2]);
                mma_bf16(acc1[1], al, bxh[1], bxh[3]);
            }

            asm volatile("cp.async.wait_group 0;" ::: "memory");
            __syncthreads();

            // ---- pass B ----
#pragma unroll
            for (int i = 0; i < 8; i++) {
                const uint32_t sc = (uint32_t)((c0 + i * 2) ^ axor) << 4;
                const uint32_t wc = (uint32_t)((c0 + i * 2) ^ bxor) << 4;
                uint32_t ah[4], al[4], bhh[4], bhl[4];
                ldm_x4(aRowH1 + sc, ah);
                ldm_x4(aRowH1 + HT32 + sc, al);
                ldm_x4(bRow + 4 * WT16 + wc, bhh);
                ldm_x4(bRow + 5 * WT16 + wc, bhl);
                mma_bf16(acc1[0], ah, bhh[0], bhh[2]);
                mma_bf16(acc1[1], ah, bhh[1], bhh[3]);
                mma_bf16(acc1[0], ah, bhl[0], bhl[2]);
                mma_bf16(acc1[1], ah, bhl[1], bhl[3]);
                mma_bf16(acc1[0], al, bhh[0], bhh[2]);
                mma_bf16(acc1[1], al, bhh[1], bhh[3]);
            }

            // ---- red ----
            {
                const int rg = lid >> 2, cc = (lid & 3) * 2;
                float* red = smf + OFF_R / 4;
                const int m = mw * 16 + rg;
#pragma unroll
                for (int nf = 0; nf < 2; nf++) {
                    const int n = nf * 8 + cc;
                    float* r0 = red + ((0 * 4 + kw) * 32 + m) * REDSTR + n;
                    float* r1 = red + ((1 * 4 + kw) * 32 + m) * REDSTR + n;
                    r0[0] = acc0[nf][0]; r0[1] = acc0[nf][1];
                    r0[8 * REDSTR] = acc0[nf][2]; r0[8 * REDSTR + 1] = acc0[nf][3];
                    r1[0] = acc1[nf][0]; r1[1] = acc1[nf][1];
                    r1[8 * REDSTR] = acc1[nf][2]; r1[8 * REDSTR + 1] = acc1[nf][3];
                }
            }
            __syncthreads();

            // ---- epilogue ----
            __half t16s[2];
            {
                float* red = smf + OFF_R / 4;
                const float* smP = smf + OFF_P / 4;
#pragma unroll
                for (int e = 0; e < 2; e++) {
                    const int row = erow + e * 16;
                    const int gbr = bg * 32 + row;
                    float s0 = 0.f, s1 = 0.f;
#pragma unroll
                    for (int q = 0; q < 4; q++) {
                        s0 += red[((0 * 4 + q) * 32 + row) * REDSTR + ecoll];
                        s1 += red[((1 * 4 + q) * 32 + row) * REDSTR + ecoll];
                    }
                    const long long o = (long long)gbr * HH + ecol;
                    if (p < SS) {
                        const float v = tanhf(s0 + smP[row * 16 + ecoll] + b0c);
                        const __nv_bfloat16 hv = __float2bfloat16(v);
                        const __nv_bfloat16 lv = __float2bfloat16(v - __bfloat162float(hv));
                        g_h0bh[p & 1][o] = hv;
                        g_h0bl[p & 1][o] = lv;
                        if (p == SS - 1) hfin[o] = v;
                    }
                    if (p >= 1) {
                        const float v = tanhf(s1 + blc);
                        const __nv_bfloat16 hv = __float2bfloat16(v);
                        const __nv_bfloat16 lv = __float2bfloat16(v - __bfloat162float(hv));
                        g_h1bh[(p + 1) & 1][o] = hv;
                        g_h1bl[(p + 1) & 1][o] = lv;
                        t16s[e] = __float2half(v);
                        if (p == SS) hfin[BB * HH + o] = v;
                    }
                }
            }

            if (p < SS) {
                __syncthreads();
                if (tid == 0) {
                    asm volatile("red.release.gpu.global.add.u32 [%0], 1;"
                                 :: "l"(gbar) : "memory");
                }
            }

            if (p >= 1) {
                const int s = p - 1;
#pragma unroll
                for (int e = 0; e < 2; e++) {
                    const int gbr = bg * 32 + erow + e * 16;
                    const long long ot = ((long long)s * BB + gbr) * HH + ecol;
                    g_T16[ot] = t16s[e];
                }
            }

            if (p < SS) {
                if (tid == 0) {
                    const unsigned int target = (unsigned)(p + 1) * 32;
                    unsigned int v;
                    do { v = ld_acq(gbar); } while (v < target);
                }
                __syncthreads();
            }
        }

        // extra arrive AFTER the final tops stores (phase SS) -> counter 129*32
        __syncthreads();
        if (tid == 0) {
            asm volatile("red.release.gpu.global.add.u32 [%0], 1;"
                         :: "l"(gbar) : "memory");
        }
    }

    // =================== logits tile drain (all 148 CTAs) ===================
    __shared__ unsigned int s_ticket;
    for (;;) {
        __syncthreads();
        if (tid == 0) s_ticket = atomicAdd(&g_ticket, 1u);
        __syncthreads();
        const unsigned int t = s_ticket;
        if (t >= N_TILES) break;
        const int mb = t / NB_N, nb = t % NB_N;

        // gate: tops(mb) final once every bg counter >= min((mb+3)*32, 129*32)
        if (tid == 0) {
            const unsigned int gate =
                (mb + 3 <= 129 ? (unsigned)(mb + 3) : 129u) * 32u;
            for (;;) {
                unsigned int m0 = ld_acq(&g_sync4[0]);
                unsigned int m1 = ld_acq(&g_sync4[32]);
                unsigned int m2 = ld_acq(&g_sync4[64]);
                unsigned int m3 = ld_acq(&g_sync4[96]);
                unsigned int mn = m0 < m1 ? m0 : m1;
                mn = mn < m2 ? mn : m2;
                mn = mn < m3 ? mn : m3;
                if (mn >= gate) break;
                __nanosleep(256);
            }
        }
        __syncthreads();

        logits_tile(sbase, mb, nb, logits, bout);
    }
}

// ---------------- prep kernels -----------------------------------------------
__global__ void prep_w0x_f16(const float* __restrict__ W0) {
    int idx = blockIdx.x * blockDim.x + threadIdx.x;
    if (idx >= HH * EE) return;
    int c = idx / EE;
    int e = idx % EE;
    g_X16[c * EE + e] = __float2half(W0[c * (HH + EE) + HH + e]);
}

__global__ void split_emb_f16(const float* __restrict__ src, float scale) {
    int i = blockIdx.x * blockDim.x + threadIdx.x;
    if (i >= VV * EE) return;
    float v = src[i] * scale;
    __half h = __float2half(v);
    g_E16h[i] = h;
    g_E16l[i] = __float2half(v - __half2float(h));
}

__global__ void conv_fp16(const float* __restrict__ src, __half* __restrict__ dst,
                          int n) {
    int i = blockIdx.x * blockDim.x + threadIdx.x;
    if (i < n) dst[i] = __float2half(src[i]);
}

__global__ void init_state(const float* __restrict__ hidden) {
    int i = blockIdx.x * blockDim.x + threadIdx.x;
    if (i == 0) g_ticket = 0;
    if (i < 128) g_sync4[i] = 0;
    if (i < BB * HH) {
        float v0 = hidden[i];
        __nv_bfloat16 h0 = __float2bfloat16(v0);
        g_h0bh[1][i] = h0;
        g_h0bl[1][i] = __float2bfloat16(v0 - __bfloat162float(h0));
        float v1 = hidden[BB * HH + i];
        __nv_bfloat16 h1 = __float2bfloat16(v1);
        g_h1bh[1][i] = h1;
        g_h1bl[1][i] = __float2bfloat16(v1 - __bfloat162float(h1));
    }
}

// ---------------- launch ------------------------------------------------------
extern "C" void kernel_launch(void* const* d_in, const int* in_sizes, int n_in,
                              void* d_out, int out_size) {
    const int*   inputs = (const int*)  d_in[0];
    const float* hidden = (const float*)d_in[1];
    const float* emb    = (const float*)d_in[2];
    const float* W0     = (const float*)d_in[3];
    const float* b0     = (const float*)d_in[4];
    const float* Wl     = (const float*)d_in[5];
    const float* bl     = (const float*)d_in[6];
    const float* Wout   = (const float*)d_in[7];
    const float* bout   = (const float*)d_in[8];

    float* logits = (float*)d_out;
    float* hfin   = (float*)d_out + (long long)SS * BB * VV;

    cudaFuncSetAttribute(gemm_fp16, cudaFuncAttributeMaxDynamicSharedMemorySize,
                         F16_SMEM);
    cudaFuncSetAttribute(rnn_fused, cudaFuncAttributeMaxDynamicSharedMemorySize,
                         RNN_SMEM);

    float* pP = nullptr;
    cudaGetSymbolAddress((void**)&pP, g_P);
    __half *pW16, *pEh, *pEl, *pX16;
    cudaGetSymbolAddress((void**)&pW16, g_W16);
    cudaGetSymbolAddress((void**)&pEh, g_E16h);
    cudaGetSymbolAddress((void**)&pEl, g_E16l);
    cudaGetSymbolAddress((void**)&pX16, g_X16);

    const float scale = 22.62741699796952f;  // sqrt(512)

    // 1. prep
    init_state<<<(BB * HH + 255) / 256, 256>>>(hidden);
    prep_w0x_f16<<<(HH * EE + 255) / 256, 256>>>(W0);
    split_emb_f16<<<(VV * EE + 255) / 256, 256>>>(emb, scale);
    conv_fp16<<<(VV * HH + 255) / 256, 256>>>(Wout, pW16, VV * HH);

    // 2. P = scale*emb @ W0x^T  (fp16 2-pass)
    {
        dim3 grid((HH + 127) / 128, (VV + 127) / 128);
        gemm_fp16<<<grid, 256, F16_SMEM>>>(pEh, pEl, pX16,
                                           VV, HH, pP, HH, nullptr);
    }

    // 3. fused: recurrence (128 worker CTAs) + logits tiles (all 148 CTAs,
    //    counter-gated ticket queue; helpers overlap with the recurrence)
    rnn_fused<<<RNN_CTAS, RNN_THR, RNN_SMEM>>>(inputs, W0, b0, Wl, bl,
                                               hfin, logits, bout);
}

// round 16
// speedup vs baseline: 1.3050x; 1.3050x over previous
#include <cuda_runtime.h>
#include <cuda_bf16.h>
#include <cuda_fp16.h>
#include <math.h>
#include <stdint.h>

#define SS 128
#define BB 128
#define VV 10000
#define HH 512
#define EE 512
#define KDIM 512

// ---------------- scratch (device globals: no allocations allowed) ----------
__device__ float g_P[VV * HH];          // scale * emb @ W0_x^T
__device__ unsigned int g_sync4[128];   // 4 batch-group barriers, 128B apart
// hidden state as bf16 hi/lo ping-pong (recurrence MMA operands)
__device__ __nv_bfloat16 g_h0bh[2][BB * HH], g_h0bl[2][BB * HH];
__device__ __nv_bfloat16 g_h1bh[2][BB * HH], g_h1bl[2][BB * HH];
// fp16 operands for the logits GEMM (single-pass)
__device__ __half g_T16[SS * BB * HH];
__device__ __half g_W16[VV * HH];
// fp16 operands for the P GEMM (A split hi/lo exact, B single)
__device__ __half g_E16h[VV * EE];
__device__ __half g_E16l[VV * EE];
__device__ __half g_X16[HH * EE];

// ============================ helpers ========================================
__device__ __forceinline__ uint32_t smem_u32(const void* p) {
    uint32_t a;
    asm("{ .reg .u64 t; cvta.to.shared.u64 t, %1; cvt.u32.u64 %0, t; }"
        : "=r"(a) : "l"(p));
    return a;
}

__device__ __forceinline__ void ldm_x4(uint32_t addr, uint32_t r[4]) {
    asm volatile("ldmatrix.sync.aligned.m8n8.x4.shared.b16 {%0,%1,%2,%3}, [%4];"
                 : "=r"(r[0]), "=r"(r[1]), "=r"(r[2]), "=r"(r[3]) : "r"(addr));
}

__device__ __forceinline__ void mma_bf16(float c[4], const uint32_t a[4],
                                         uint32_t b0, uint32_t b1) {
    asm volatile(
        "mma.sync.aligned.m16n8k16.row.col.f32.bf16.bf16.f32 "
        "{%0,%1,%2,%3}, {%4,%5,%6,%7}, {%8,%9}, {%0,%1,%2,%3};"
        : "+f"(c[0]), "+f"(c[1]), "+f"(c[2]), "+f"(c[3])
        : "r"(a[0]), "r"(a[1]), "r"(a[2]), "r"(a[3]), "r"(b0), "r"(b1));
}

__device__ __forceinline__ void mma_fp16(float c[4], const uint32_t a[4],
                                         uint32_t b0, uint32_t b1) {
    asm volatile(
        "mma.sync.aligned.m16n8k16.row.col.f32.f16.f16.f32 "
        "{%0,%1,%2,%3}, {%4,%5,%6,%7}, {%8,%9}, {%0,%1,%2,%3};"
        : "+f"(c[0]), "+f"(c[1]), "+f"(c[2]), "+f"(c[3])
        : "r"(a[0]), "r"(a[1]), "r"(a[2]), "r"(a[3]), "r"(b0), "r"(b1));
}

#define BK 32
#define ROWB 80
#define TILE_SB (128 * ROWB)
#define KT_N (KDIM / BK)               // 16

// =================== fp16 2-pass HMMA GEMM (P matrix) ========================
#define F16_STAGE (3 * TILE_SB)          // 30720
#define F16_SMEM (2 * F16_STAGE)         // 61440

__global__ __launch_bounds__(256, 2)
void gemm_fp16(const __half* __restrict__ Ahi,
               const __half* __restrict__ Alo,
               const __half* __restrict__ Bh,
               int M, int N, float* __restrict__ C, int ldc,
               const float* __restrict__ bias) {
    extern __shared__ char smem[];
    const uint32_t sb = smem_u32(smem);
    const int tid = threadIdx.x;
    const int wid = tid >> 5, lid = tid & 31;
    const int wm = wid & 3, wn = wid >> 2;
    const int nb = blockIdx.x, mb = blockIdx.y;

    const __half* __restrict__ srcs[3] = {Ahi, Alo, Bh};

    float acc[2][8][4];
#pragma unroll
    for (int i = 0; i < 2; i++)
#pragma unroll
        for (int j = 0; j < 8; j++)
#pragma unroll
            for (int q = 0; q < 4; q++) acc[i][j][q] = 0.0f;

    auto load_stage = [&](int st, int kt) {
#pragma unroll
        for (int t = 0; t < 3; t++) {
#pragma unroll
            for (int i = 0; i < 2; i++) {
                const int idx = tid + i * 256;
                const int row = idx >> 2, ch = idx & 3;
                const long long grow =
                    (t < 2) ? (long long)mb * 128 + row : (long long)nb * 128 + row;
                const bool ok = (t < 2) ? (grow < M) : (grow < N);
                const __half* src = srcs[t] + grow * KDIM + kt * BK + ch * 8;
                const uint32_t dst = sb + st * F16_STAGE + t * TILE_SB + row * ROWB + ch * 16;
                const int sz = ok ? 16 : 0;
                asm volatile("cp.async.cg.shared.global [%0], [%1], 16, %2;"
                             :: "r"(dst), "l"(src), "r"(sz) : "memory");
            }
        }
        asm volatile("cp.async.commit_group;" ::: "memory");
    };

    const int lr = lid & 15;
    const int lc = lid >> 4;

    load_stage(0, 0);

    for (int kt = 0; kt < KT_N; kt++) {
        const int st = kt & 1;
        if (kt + 1 < KT_N) {
            load_stage(st ^ 1, kt + 1);
            asm volatile("cp.async.wait_group 1;" ::: "memory");
        } else {
            asm volatile("cp.async.wait_group 0;" ::: "memory");
        }
        __syncthreads();

        const uint32_t stg = sb + st * F16_STAGE;
        const uint32_t aBaseHi = stg + 0 * TILE_SB;
        const uint32_t aBaseLo = stg + 1 * TILE_SB;
        const uint32_t bBase = stg + 2 * TILE_SB;

#pragma unroll
        for (int k16 = 0; k16 < 2; k16++) {
            const uint32_t koff = k16 * 32 + lc * 16;

            uint32_t ahi[2][4], alo[2][4];
#pragma unroll
            for (int mf = 0; mf < 2; mf++) {
                const uint32_t roff = (uint32_t)(wm * 32 + mf * 16 + lr) * ROWB + koff;
                ldm_x4(aBaseHi + roff, ahi[mf]);
                ldm_x4(aBaseLo + roff, alo[mf]);
            }
#pragma unroll
            for (int reg = 0; reg < 4; reg++) {
                const uint32_t roff = (uint32_t)(wn * 64 + reg * 16 + lr) * ROWB + koff;
                uint32_t bh[4];
                ldm_x4(bBase + roff, bh);
#pragma unroll
                for (int mf = 0; mf < 2; mf++) {
                    mma_fp16(acc[mf][reg * 2 + 0], ahi[mf], bh[0], bh[2]);
                    mma_fp16(acc[mf][reg * 2 + 0], alo[mf], bh[0], bh[2]);
                    mma_fp16(acc[mf][reg * 2 + 1], ahi[mf], bh[1], bh[3]);
                    mma_fp16(acc[mf][reg * 2 + 1], alo[mf], bh[1], bh[3]);
                }
            }
        }
        __syncthreads();
    }

    const int lr4 = lid >> 2;
    const int lc2 = (lid & 3) * 2;
#pragma unroll
    for (int mf = 0; mf < 2; mf++) {
#pragma unroll
        for (int nf = 0; nf < 8; nf++) {
            const int m = mb * 128 + wm * 32 + mf * 16 + lr4;
            const int n = nb * 128 + wn * 64 + nf * 8 + lc2;
            if (n >= N) continue;
            float b0 = 0.f, b1 = 0.f;
            if (bias) { b0 = bias[n]; b1 = bias[n + 1]; }
            if (m < M) {
                float2 v = make_float2(acc[mf][nf][0] + b0, acc[mf][nf][1] + b1);
                *reinterpret_cast<float2*>(C + (long long)m * ldc + n) = v;
            }
            if (m + 8 < M) {
                float2 v = make_float2(acc[mf][nf][2] + b0, acc[mf][nf][3] + b1);
                *reinterpret_cast<float2*>(C + (long long)(m + 8) * ldc + n) = v;
            }
        }
    }
}

// =================== fp16 SINGLE-pass HMMA GEMM (logits) =====================
#define F161_STAGE (2 * TILE_SB)         // 20480
#define F161_SMEM (2 * F161_STAGE)       // 40960

__global__ __launch_bounds__(256, 2)
void gemm_f16_1p(const __half* __restrict__ A16,
                 const __half* __restrict__ B16,
                 int M, int N, float* __restrict__ C, int ldc,
                 const float* __restrict__ bias) {
    extern __shared__ char smem[];
    const uint32_t sb = smem_u32(smem);
    const int tid = threadIdx.x;
    const int wid = tid >> 5, lid = tid & 31;
    const int wm = wid & 3, wn = wid >> 2;
    const int nb = blockIdx.x, mb = blockIdx.y;

    float acc[2][8][4];
#pragma unroll
    for (int i = 0; i < 2; i++)
#pragma unroll
        for (int j = 0; j < 8; j++)
#pragma unroll
            for (int q = 0; q < 4; q++) acc[i][j][q] = 0.0f;

    auto load_stage = [&](int st, int kt) {
#pragma unroll
        for (int t = 0; t < 2; t++) {
#pragma unroll
            for (int i = 0; i < 2; i++) {
                const int idx = tid + i * 256;
                const int row = idx >> 2, ch = idx & 3;
                const long long grow =
                    (t == 0) ? (long long)mb * 128 + row : (long long)nb * 128 + row;
                const bool ok = (t == 0) ? (grow < M) : (grow < N);
                const __half* src = (t == 0 ? A16 : B16) + grow * KDIM + kt * BK + ch * 8;
                const uint32_t dst = sb + st * F161_STAGE + t * TILE_SB + row * ROWB + ch * 16;
                const int sz = ok ? 16 : 0;
                asm volatile("cp.async.cg.shared.global [%0], [%1], 16, %2;"
                             :: "r"(dst), "l"(src), "r"(sz) : "memory");
            }
        }
        asm volatile("cp.async.commit_group;" ::: "memory");
    };

    const int lr = lid & 15;
    const int lc = lid >> 4;

    load_stage(0, 0);

    for (int kt = 0; kt < KT_N; kt++) {
        const int st = kt & 1;
        if (kt + 1 < KT_N) {
            load_stage(st ^ 1, kt + 1);
            asm volatile("cp.async.wait_group 1;" ::: "memory");
        } else {
            asm volatile("cp.async.wait_group 0;" ::: "memory");
        }
        __syncthreads();

        const uint32_t stg = sb + st * F161_STAGE;
        const uint32_t aBase = stg;
        const uint32_t bBase = stg + TILE_SB;

#pragma unroll
        for (int k16 = 0; k16 < 2; k16++) {
            const uint32_t koff = k16 * 32 + lc * 16;

            uint32_t af[2][4];
#pragma unroll
            for (int mf = 0; mf < 2; mf++) {
                const uint32_t roff = (uint32_t)(wm * 32 + mf * 16 + lr) * ROWB + koff;
                ldm_x4(aBase + roff, af[mf]);
            }
#pragma unroll
            for (int reg = 0; reg < 4; reg++) {
                const uint32_t roff = (uint32_t)(wn * 64 + reg * 16 + lr) * ROWB + koff;
                uint32_t bh[4];
                ldm_x4(bBase + roff, bh);
#pragma unroll
                for (int mf = 0; mf < 2; mf++) {
                    mma_fp16(acc[mf][reg * 2 + 0], af[mf], bh[0], bh[2]);
                    mma_fp16(acc[mf][reg * 2 + 1], af[mf], bh[1], bh[3]);
                }
            }
        }
        __syncthreads();
    }

    const int lr4 = lid >> 2;
    const int lc2 = (lid & 3) * 2;
#pragma unroll
    for (int mf = 0; mf < 2; mf++) {
#pragma unroll
        for (int nf = 0; nf < 8; nf++) {
            const int m = mb * 128 + wm * 32 + mf * 16 + lr4;
            const int n = nb * 128 + wn * 64 + nf * 8 + lc2;
            if (n >= N) continue;
            float b0 = 0.f, b1 = 0.f;
            if (bias) { b0 = bias[n]; b1 = bias[n + 1]; }
            if (m < M) {
                float2 v = make_float2(acc[mf][nf][0] + b0, acc[mf][nf][1] + b1);
                *reinterpret_cast<float2*>(C + (long long)m * ldc + n) = v;
            }
            if (m + 8 < M) {
                float2 v = make_float2(acc[mf][nf][2] + b0, acc[mf][nf][3] + b1);
                *reinterpret_cast<float2*>(C + (long long)(m + 8) * ldc + n) = v;
            }
        }
    }
}

// =================== persistent recurrence kernel v7 (512 threads) ==========
// 128 CTAs = 4 bg(32 batch rows) x 32 cg(16 out cols). 512 threads = 16 warps
// (2 m-frags x 8 k-slices): per-warp MMA count halved vs v5, 4 warps/SMSP
// for latency hiding. Epilogue: exactly 1 cell per thread (32x16 = 512).

#define RNN_CTAS 128
#define RNN_THR 512
#define WT16 16384
#define HT32 32768
#define OFF_W 0
#define OFF_H0 (6 * WT16)
#define OFF_H1 (OFF_H0 + 2 * HT32)
#define OFF_P (OFF_H1 + 2 * HT32)         // 229376: P prefetch, 32x16 fp32
#define RNN_SMEM (OFF_P + 2048)           // 231424
#define OFF_R OFF_H0
#define REDSTR 17

__global__ __launch_bounds__(RNN_THR, 1)
void rnn_persist(const int* __restrict__ inputs,
                 const float* __restrict__ W0,
                 const float* __restrict__ b0,
                 const float* __restrict__ Wl,
                 const float* __restrict__ bl,
                 float* __restrict__ hfin) {
    extern __shared__ char smc[];
    const uint32_t sbase = smem_u32(smc);
    float* const smf = reinterpret_cast<float*>(smc);
    const int tid = threadIdx.x;
    const int wid = tid >> 5, lid = tid & 31;
    const int bg = blockIdx.x >> 5;
    const int cg = blockIdx.x & 31;
    const int cbase = cg * 16;

    // ---- split weight slices into smem bf16 hi/lo tiles (once, swizzled) ----
    for (int i = tid; i < 16 * 512; i += RNN_THR) {
        const int r = i >> 9, k = i & 511;
        const int gc = cbase + r;
        const uint32_t off = r * 1024 + (((k >> 3) ^ (r & 7)) << 4) + (k & 7) * 2;
        float v[3];
        v[0] = W0[gc * 1024 + k];
        v[1] = Wl[gc * 1024 + 512 + k];
        v[2] = Wl[gc * 1024 + k];
#pragma unroll
        for (int t = 0; t < 3; t++) {
            const __nv_bfloat16 hi = __float2bfloat16(v[t]);
            const __nv_bfloat16 lo = __float2bfloat16(v[t] - __bfloat162float(hi));
            char* base = smc + OFF_W + (2 * t) * WT16 + off;
            *reinterpret_cast<__nv_bfloat16*>(base) = hi;
            *reinterpret_cast<__nv_bfloat16*>(base + WT16) = lo;
        }
    }
    __syncthreads();

    const int mw = wid & 1;                // m-frag: rows mw*16..+15
    const int kw = wid >> 1;               // k-slice 0..7 (8 chunks each)
    const int lr = lid & 15, lc = lid >> 4;

    const int ecoll = tid & 15, erow = (tid >> 4) & 31;   // 1 cell per thread
    const int ecol = cbase + ecoll;
    const float b0c = b0[ecol], blc = bl[ecol];

    const int arow = mw * 16 + lr;
    const uint32_t aRowH0 = sbase + OFF_H0 + arow * 1024;
    const uint32_t aRowH1 = sbase + OFF_H1 + arow * 1024;
    const uint32_t bRow = sbase + OFF_W + lr * 1024;
    const int axor = arow & 7;
    const int bxor = lr & 7;
    const int c0 = kw * 8 + lc;            // 8 chunks per k-slice, 4 iters x 2

    unsigned int* const gbar = &g_sync4[bg * 32];

    auto stage_h = [&](uint32_t offBase, const __nv_bfloat16* hi,
                       const __nv_bfloat16* lo) {
#pragma unroll
        for (int j = 0; j < 8; j++) {
            const int idx = tid + j * 512;       // 4096 16B tiles
            const int tile = idx >> 11;
            const int c = idx & 2047;
            const int row = c >> 6, ch = c & 63;
            const __nv_bfloat16* src =
                (tile ? lo : hi) + (long long)(bg * 32 + row) * HH + ch * 8;
            const uint32_t dst = sbase + offBase + tile * HT32 + row * 1024 +
                                 ((ch ^ (row & 7)) << 4);
            asm volatile("cp.async.cg.shared.global [%0], [%1], 16;"
                         :: "r"(dst), "l"(src) : "memory");
        }
        asm volatile("cp.async.commit_group;" ::: "memory");
    };

    for (int p = 0; p <= SS; p++) {
        float acc0[2][4] = {{0, 0, 0, 0}, {0, 0, 0, 0}};
        float acc1[2][4] = {{0, 0, 0, 0}, {0, 0, 0, 0}};

        if (p < SS && tid < 128) {
            const int row = tid >> 2, ch = tid & 3;
            const int tok = __ldg(inputs + p * BB + bg * 32 + row);
            const float* src = g_P + (long long)tok * HH + cbase + ch * 4;
            const uint32_t dst = sbase + OFF_P + row * 64 + ch * 16;
            asm volatile("cp.async.cg.shared.global [%0], [%1], 16;"
                         :: "r"(dst), "l"(src) : "memory");
        }
        stage_h(OFF_H0, g_h0bh[(p + 1) & 1], g_h0bl[(p + 1) & 1]);
        stage_h(OFF_H1, g_h1bh[p & 1], g_h1bl[p & 1]);
        asm volatile("cp.async.wait_group 1;" ::: "memory");   // P+h0 ready
        __syncthreads();

        // ---- pass A: h0 x W0h -> acc0 ; h0 x Wlx -> acc1 (4 iters/warp) ----
#pragma unroll
        for (int i = 0; i < 4; i++) {
            const uint32_t sc = (uint32_t)((c0 + i * 2) ^ axor) << 4;
            const uint32_t wc = (uint32_t)((c0 + i * 2) ^ bxor) << 4;
            uint32_t ah[4], al[4], b0h[4], b0l[4], bxh[4], bxl[4];
            ldm_x4(aRowH0 + sc, ah);
            ldm_x4(aRowH0 + HT32 + sc, al);
            ldm_x4(bRow + 0 * WT16 + wc, b0h);
            ldm_x4(bRow + 1 * WT16 + wc, b0l);
            ldm_x4(bRow + 2 * WT16 + wc, bxh);
            ldm_x4(bRow + 3 * WT16 + wc, bxl);
            mma_bf16(acc0[0], ah, b0h[0], b0h[2]);
            mma_bf16(acc0[1], ah, b0h[1], b0h[3]);
            mma_bf16(acc0[0], ah, b0l[0], b0l[2]);
            mma_bf16(acc0[1], ah, b0l[1], b0l[3]);
            mma_bf16(acc0[0], al, b0h[0], b0h[2]);
            mma_bf16(acc0[1], al, b0h[1], b0h[3]);
            mma_bf16(acc1[0], ah, bxh[0], bxh[2]);
            mma_bf16(acc1[1], ah, bxh[1], bxh[3]);
            mma_bf16(acc1[0], ah, bxl[0], bxl[2]);
            mma_bf16(acc1[1], ah, bxl[1], bxl[3]);
            mma_bf16(acc1[0], al, bxh[0], bxh[2]);
            mma_bf16(acc1[1], al, bxh[1], bxh[3]);
        }

        asm volatile("cp.async.wait_group 0;" ::: "memory");   // h1 ready
        __syncthreads();

        // ---- pass B: h1 x Wlh -> acc1 ----
#pragma unroll
        for (int i = 0; i < 4; i++) {
            const uint32_t sc = (uint32_t)((c0 + i * 2) ^ axor) << 4;
            const uint32_t wc = (uint32_t)((c0 + i * 2) ^ bxor) << 4;
            uint32_t ah[4], al[4], bhh[4], bhl[4];
            ldm_x4(aRowH1 + sc, ah);
            ldm_x4(aRowH1 + HT32 + sc, al);
            ldm_x4(bRow + 4 * WT16 + wc, bhh);
            ldm_x4(bRow + 5 * WT16 + wc, bhl);
            mma_bf16(acc1[0], ah, bhh[0], bhh[2]);
            mma_bf16(acc1[1], ah, bhh[1], bhh[3]);
            mma_bf16(acc1[0], ah, bhl[0], bhl[2]);
            mma_bf16(acc1[1], ah, bhl[1], bhl[3]);
            mma_bf16(acc1[0], al, bhh[0], bhh[2]);
            mma_bf16(acc1[1], al, bhh[1], bhh[3]);
        }

        // ---- write k-slice frags to red (aliases h0 buffer; 8 slices) ----
        {
            const int rg = lid >> 2, cc = (lid & 3) * 2;
            float* red = smf + OFF_R / 4;
            const int m = mw * 16 + rg;
#pragma unroll
            for (int nf = 0; nf < 2; nf++) {
                const int n = nf * 8 + cc;
                float* r0 = red + ((0 * 8 + kw) * 32 + m) * REDSTR + n;
                float* r1 = red + ((1 * 8 + kw) * 32 + m) * REDSTR + n;
                r0[0] = acc0[nf][0]; r0[1] = acc0[nf][1];
                r0[8 * REDSTR] = acc0[nf][2]; r0[8 * REDSTR + 1] = acc0[nf][3];
                r1[0] = acc1[nf][0]; r1[1] = acc1[nf][1];
                r1[8 * REDSTR] = acc1[nf][2]; r1[8 * REDSTR + 1] = acc1[nf][3];
            }
        }
        __syncthreads();

        // ---- epilogue: 1 cell per thread ----
        __half t16v;
        {
            float* red = smf + OFF_R / 4;
            const float* smP = smf + OFF_P / 4;
            const int row = erow;
            const int gbr = bg * 32 + row;
            float s0 = 0.f, s1 = 0.f;
#pragma unroll
            for (int q = 0; q < 8; q++) {
                s0 += red[((0 * 8 + q) * 32 + row) * REDSTR + ecoll];
                s1 += red[((1 * 8 + q) * 32 + row) * REDSTR + ecoll];
            }
            const long long o = (long long)gbr * HH + ecol;
            if (p < SS) {
                const float v = tanhf(s0 + smP[row * 16 + ecoll] + b0c);
                const __nv_bfloat16 hv = __float2bfloat16(v);
                const __nv_bfloat16 lv = __float2bfloat16(v - __bfloat162float(hv));
                g_h0bh[p & 1][o] = hv;
                g_h0bl[p & 1][o] = lv;
                if (p == SS - 1) hfin[o] = v;
            }
            if (p >= 1) {
                const float v = tanhf(s1 + blc);
                const __nv_bfloat16 hv = __float2bfloat16(v);
                const __nv_bfloat16 lv = __float2bfloat16(v - __bfloat162float(hv));
                g_h1bh[(p + 1) & 1][o] = hv;
                g_h1bl[(p + 1) & 1][o] = lv;
                t16v = __float2half(v);
                if (p == SS) hfin[BB * HH + o] = v;
            }
        }

        // arrive on the bg-local barrier BEFORE the tops stores
        if (p < SS) {
            __syncthreads();
            if (tid == 0) {
                asm volatile("red.release.gpu.global.add.u32 [%0], 1;"
                             :: "l"(gbar) : "memory");
            }
        }

        if (p >= 1) {
            const int s = p - 1;
            const int gbr = bg * 32 + erow;
            const long long ot = ((long long)s * BB + gbr) * HH + ecol;
            g_T16[ot] = t16v;
        }

        if (p < SS) {
            if (tid == 0) {
                const unsigned int target = (unsigned)(p + 1) * 32;
                unsigned int v;
                do {
                    asm volatile("ld.acquire.gpu.global.u32 %0, [%1];"
                                 : "=r"(v) : "l"(gbar) : "memory");
                } while (v < target);
            }
            __syncthreads();
        }
    }
}

// ---------------- prep kernels -----------------------------------------------
__global__ void prep_w0x_f16(const float* __restrict__ W0) {
    int idx = blockIdx.x * blockDim.x + threadIdx.x;
    if (idx >= HH * EE) return;
    int c = idx / EE;
    int e = idx % EE;
    g_X16[c * EE + e] = __float2half(W0[c * (HH + EE) + HH + e]);
}

__global__ void split_emb_f16(const float* __restrict__ src, float scale) {
    int i = blockIdx.x * blockDim.x + threadIdx.x;
    if (i >= VV * EE) return;
    float v = src[i] * scale;
    __half h = __float2half(v);
    g_E16h[i] = h;
    g_E16l[i] = __float2half(v - __half2float(h));
}

__global__ void conv_fp16(const float* __restrict__ src, __half* __restrict__ dst,
                          int n) {
    int i = blockIdx.x * blockDim.x + threadIdx.x;
    if (i < n) dst[i] = __float2half(src[i]);
}

__global__ void init_state(const float* __restrict__ hidden) {
    int i = blockIdx.x * blockDim.x + threadIdx.x;
    if (i < 128) g_sync4[i] = 0;
    if (i < BB * HH) {
        float v0 = hidden[i];
        __nv_bfloat16 h0 = __float2bfloat16(v0);
        g_h0bh[1][i] = h0;
        g_h0bl[1][i] = __float2bfloat16(v0 - __bfloat162float(h0));
        float v1 = hidden[BB * HH + i];
        __nv_bfloat16 h1 = __float2bfloat16(v1);
        g_h1bh[1][i] = h1;
        g_h1bl[1][i] = __float2bfloat16(v1 - __bfloat162float(h1));
    }
}

// ---------------- launch ------------------------------------------------------
extern "C" void kernel_launch(void* const* d_in, const int* in_sizes, int n_in,
                              void* d_out, int out_size) {
    const int*   inputs = (const int*)  d_in[0];
    const float* hidden = (const float*)d_in[1];
    const float* emb    = (const float*)d_in[2];
    const float* W0     = (const float*)d_in[3];
    const float* b0     = (const float*)d_in[4];
    const float* Wl     = (const float*)d_in[5];
    const float* bl     = (const float*)d_in[6];
    const float* Wout   = (const float*)d_in[7];
    const float* bout   = (const float*)d_in[8];

    float* logits = (float*)d_out;
    float* hfin   = (float*)d_out + (long long)SS * BB * VV;

    cudaFuncSetAttribute(gemm_fp16, cudaFuncAttributeMaxDynamicSharedMemorySize,
                         F16_SMEM);
    cudaFuncSetAttribute(gemm_f16_1p, cudaFuncAttributeMaxDynamicSharedMemorySize,
                         F161_SMEM);
    cudaFuncSetAttribute(rnn_persist, cudaFuncAttributeMaxDynamicSharedMemorySize,
                         RNN_SMEM);

    float* pP = nullptr;
    cudaGetSymbolAddress((void**)&pP, g_P);
    __half *pT16, *pW16, *pEh, *pEl, *pX16;
    cudaGetSymbolAddress((void**)&pT16, g_T16);
    cudaGetSymbolAddress((void**)&pW16, g_W16);
    cudaGetSymbolAddress((void**)&pEh, g_E16h);
    cudaGetSymbolAddress((void**)&pEl, g_E16l);
    cudaGetSymbolAddress((void**)&pX16, g_X16);

    const float scale = 22.62741699796952f;  // sqrt(512)

    // 1. prep
    init_state<<<(BB * HH + 255) / 256, 256>>>(hidden);
    prep_w0x_f16<<<(HH * EE + 255) / 256, 256>>>(W0);
    split_emb_f16<<<(VV * EE + 255) / 256, 256>>>(emb, scale);
    conv_fp16<<<(VV * HH + 255) / 256, 256>>>(Wout, pW16, VV * HH);

    // 2. P = scale*emb @ W0x^T  (fp16 2-pass)
    {
        dim3 grid((HH + 127) / 128, (VV + 127) / 128);
        gemm_fp16<<<grid, 256, F16_SMEM>>>(pEh, pEl, pX16,
                                           VV, HH, pP, HH, nullptr);
    }

    // 3. recurrence (512-thread persistent kernel)
    rnn_persist<<<RNN_CTAS, RNN_THR, RNN_SMEM>>>(inputs, W0, b0, Wl, bl, hfin);

    // 4. logits = tops @ Wout^T + bout  (fp16 single-pass)
    {
        dim3 grid((VV + 127) / 128, (SS * BB + 127) / 128);
        gemm_f16_1p<<<grid, 256, F161_SMEM>>>(pT16, pW16,
                                              SS * BB, VV, logits, VV, bout);
    }
}

// round 17
// speedup vs baseline: 1.3568x; 1.0397x over previous
#include <cuda_runtime.h>
#include <cuda_bf16.h>
#include <cuda_fp16.h>
#include <math.h>
#include <stdint.h>

#define SS 128
#define BB 128
#define VV 10000
#define HH 512
#define EE 512
#define KDIM 512

// ---------------- scratch (device globals: no allocations allowed) ----------
__device__ float g_P[VV * HH];          // scale * emb @ W0_x^T
__device__ unsigned int g_sync4[128];   // 4 batch-group barriers, 128B apart
// hidden state as bf16 hi/lo ping-pong (recurrence MMA operands)
__device__ __nv_bfloat16 g_h0bh[2][BB * HH], g_h0bl[2][BB * HH];
__device__ __nv_bfloat16 g_h1bh[2][BB * HH], g_h1bl[2][BB * HH];
// fp16 operands for the logits GEMM (single-pass)
__device__ __half g_T16[SS * BB * HH];
__device__ __half g_W16[VV * HH];
// fp16 operands for the P GEMM (A split hi/lo exact, B single)
__device__ __half g_E16h[VV * EE];
__device__ __half g_E16l[VV * EE];
__device__ __half g_X16[HH * EE];

// ============================ helpers ========================================
__device__ __forceinline__ uint32_t smem_u32(const void* p) {
    uint32_t a;
    asm("{ .reg .u64 t; cvta.to.shared.u64 t, %1; cvt.u32.u64 %0, t; }"
        : "=r"(a) : "l"(p));
    return a;
}

__device__ __forceinline__ void ldm_x4(uint32_t addr, uint32_t r[4]) {
    asm volatile("ldmatrix.sync.aligned.m8n8.x4.shared.b16 {%0,%1,%2,%3}, [%4];"
                 : "=r"(r[0]), "=r"(r[1]), "=r"(r[2]), "=r"(r[3]) : "r"(addr));
}

__device__ __forceinline__ void mma_bf16(float c[4], const uint32_t a[4],
                                         uint32_t b0, uint32_t b1) {
    asm volatile(
        "mma.sync.aligned.m16n8k16.row.col.f32.bf16.bf16.f32 "
        "{%0,%1,%2,%3}, {%4,%5,%6,%7}, {%8,%9}, {%0,%1,%2,%3};"
        : "+f"(c[0]), "+f"(c[1]), "+f"(c[2]), "+f"(c[3])
        : "r"(a[0]), "r"(a[1]), "r"(a[2]), "r"(a[3]), "r"(b0), "r"(b1));
}

__device__ __forceinline__ void mma_fp16(float c[4], const uint32_t a[4],
                                         uint32_t b0, uint32_t b1) {
    asm volatile(
        "mma.sync.aligned.m16n8k16.row.col.f32.f16.f16.f32 "
        "{%0,%1,%2,%3}, {%4,%5,%6,%7}, {%8,%9}, {%0,%1,%2,%3};"
        : "+f"(c[0]), "+f"(c[1]), "+f"(c[2]), "+f"(c[3])
        : "r"(a[0]), "r"(a[1]), "r"(a[2]), "r"(a[3]), "r"(b0), "r"(b1));
}

#define BK 32
#define ROWB 80
#define TILE_SB (128 * ROWB)
#define KT_N (KDIM / BK)               // 16

// =================== fp16 2-pass HMMA GEMM (P matrix) ========================
#define F16_STAGE (3 * TILE_SB)          // 30720
#define F16_SMEM (2 * F16_STAGE)         // 61440

__global__ __launch_bounds__(256, 2)
void gemm_fp16(const __half* __restrict__ Ahi,
               const __half* __restrict__ Alo,
               const __half* __restrict__ Bh,
               int M, int N, float* __restrict__ C, int ldc,
               const float* __restrict__ bias) {
    extern __shared__ char smem[];
    const uint32_t sb = smem_u32(smem);
    const int tid = threadIdx.x;
    const int wid = tid >> 5, lid = tid & 31;
    const int wm = wid & 3, wn = wid >> 2;
    const int nb = blockIdx.x, mb = blockIdx.y;

    const __half* __restrict__ srcs[3] = {Ahi, Alo, Bh};

    float acc[2][8][4];
#pragma unroll
    for (int i = 0; i < 2; i++)
#pragma unroll
        for (int j = 0; j < 8; j++)
#pragma unroll
            for (int q = 0; q < 4; q++) acc[i][j][q] = 0.0f;

    auto load_stage = [&](int st, int kt) {
#pragma unroll
        for (int t = 0; t < 3; t++) {
#pragma unroll
            for (int i = 0; i < 2; i++) {
                const int idx = tid + i * 256;
                const int row = idx >> 2, ch = idx & 3;
                const long long grow =
                    (t < 2) ? (long long)mb * 128 + row : (long long)nb * 128 + row;
                const bool ok = (t < 2) ? (grow < M) : (grow < N);
                const __half* src = srcs[t] + grow * KDIM + kt * BK + ch * 8;
                const uint32_t dst = sb + st * F16_STAGE + t * TILE_SB + row * ROWB + ch * 16;
                const int sz = ok ? 16 : 0;
                asm volatile("cp.async.cg.shared.global [%0], [%1], 16, %2;"
                             :: "r"(dst), "l"(src), "r"(sz) : "memory");
            }
        }
        asm volatile("cp.async.commit_group;" ::: "memory");
    };

    const int lr = lid & 15;
    const int lc = lid >> 4;

    load_stage(0, 0);

    for (int kt = 0; kt < KT_N; kt++) {
        const int st = kt & 1;
        if (kt + 1 < KT_N) {
            load_stage(st ^ 1, kt + 1);
            asm volatile("cp.async.wait_group 1;" ::: "memory");
        } else {
            asm volatile("cp.async.wait_group 0;" ::: "memory");
        }
        __syncthreads();

        const uint32_t stg = sb + st * F16_STAGE;
        const uint32_t aBaseHi = stg + 0 * TILE_SB;
        const uint32_t aBaseLo = stg + 1 * TILE_SB;
        const uint32_t bBase = stg + 2 * TILE_SB;

#pragma unroll
        for (int k16 = 0; k16 < 2; k16++) {
            const uint32_t koff = k16 * 32 + lc * 16;

            uint32_t ahi[2][4], alo[2][4];
#pragma unroll
            for (int mf = 0; mf < 2; mf++) {
                const uint32_t roff = (uint32_t)(wm * 32 + mf * 16 + lr) * ROWB + koff;
                ldm_x4(aBaseHi + roff, ahi[mf]);
                ldm_x4(aBaseLo + roff, alo[mf]);
            }
#pragma unroll
            for (int reg = 0; reg < 4; reg++) {
                const uint32_t roff = (uint32_t)(wn * 64 + reg * 16 + lr) * ROWB + koff;
                uint32_t bh[4];
                ldm_x4(bBase + roff, bh);
#pragma unroll
                for (int mf = 0; mf < 2; mf++) {
                    mma_fp16(acc[mf][reg * 2 + 0], ahi[mf], bh[0], bh[2]);
                    mma_fp16(acc[mf][reg * 2 + 0], alo[mf], bh[0], bh[2]);
                    mma_fp16(acc[mf][reg * 2 + 1], ahi[mf], bh[1], bh[3]);
                    mma_fp16(acc[mf][reg * 2 + 1], alo[mf], bh[1], bh[3]);
                }
            }
        }
        __syncthreads();
    }

    const int lr4 = lid >> 2;
    const int lc2 = (lid & 3) * 2;
#pragma unroll
    for (int mf = 0; mf < 2; mf++) {
#pragma unroll
        for (int nf = 0; nf < 8; nf++) {
            const int m = mb * 128 + wm * 32 + mf * 16 + lr4;
            const int n = nb * 128 + wn * 64 + nf * 8 + lc2;
            if (n >= N) continue;
            float b0 = 0.f, b1 = 0.f;
            if (bias) { b0 = bias[n]; b1 = bias[n + 1]; }
            if (m < M) {
                float2 v = make_float2(acc[mf][nf][0] + b0, acc[mf][nf][1] + b1);
                *reinterpret_cast<float2*>(C + (long long)m * ldc + n) = v;
            }
            if (m + 8 < M) {
                float2 v = make_float2(acc[mf][nf][2] + b0, acc[mf][nf][3] + b1);
                *reinterpret_cast<float2*>(C + (long long)(m + 8) * ldc + n) = v;
            }
        }
    }
}

// =================== fp16 SINGLE-pass HMMA GEMM (logits) =====================
#define F161_STAGE (2 * TILE_SB)         // 20480
#define F161_SMEM (2 * F161_STAGE)       // 40960

__global__ __launch_bounds__(256, 2)
void gemm_f16_1p(const __half* __restrict__ A16,
                 const __half* __restrict__ B16,
                 int M, int N, float* __restrict__ C, int ldc,
                 const float* __restrict__ bias) {
    extern __shared__ char smem[];
    const uint32_t sb = smem_u32(smem);
    const int tid = threadIdx.x;
    const int wid = tid >> 5, lid = tid & 31;
    const int wm = wid & 3, wn = wid >> 2;
    const int nb = blockIdx.x, mb = blockIdx.y;

    float acc[2][8][4];
#pragma unroll
    for (int i = 0; i < 2; i++)
#pragma unroll
        for (int j = 0; j < 8; j++)
#pragma unroll
            for (int q = 0; q < 4; q++) acc[i][j][q] = 0.0f;

    auto load_stage = [&](int st, int kt) {
#pragma unroll
        for (int t = 0; t < 2; t++) {
#pragma unroll
            for (int i = 0; i < 2; i++) {
                const int idx = tid + i * 256;
                const int row = idx >> 2, ch = idx & 3;
                const long long grow =
                    (t == 0) ? (long long)mb * 128 + row : (long long)nb * 128 + row;
                const bool ok = (t == 0) ? (grow < M) : (grow < N);
                const __half* src = (t == 0 ? A16 : B16) + grow * KDIM + kt * BK + ch * 8;
                const uint32_t dst = sb + st * F161_STAGE + t * TILE_SB + row * ROWB + ch * 16;
                const int sz = ok ? 16 : 0;
                asm volatile("cp.async.cg.shared.global [%0], [%1], 16, %2;"
                             :: "r"(dst), "l"(src), "r"(sz) : "memory");
            }
        }
        asm volatile("cp.async.commit_group;" ::: "memory");
    };

    const int lr = lid & 15;
    const int lc = lid >> 4;

    load_stage(0, 0);

    for (int kt = 0; kt < KT_N; kt++) {
        const int st = kt & 1;
        if (kt + 1 < KT_N) {
            load_stage(st ^ 1, kt + 1);
            asm volatile("cp.async.wait_group 1;" ::: "memory");
        } else {
            asm volatile("cp.async.wait_group 0;" ::: "memory");
        }
        __syncthreads();

        const uint32_t stg = sb + st * F161_STAGE;
        const uint32_t aBase = stg;
        const uint32_t bBase = stg + TILE_SB;

#pragma unroll
        for (int k16 = 0; k16 < 2; k16++) {
            const uint32_t koff = k16 * 32 + lc * 16;

            uint32_t af[2][4];
#pragma unroll
            for (int mf = 0; mf < 2; mf++) {
                const uint32_t roff = (uint32_t)(wm * 32 + mf * 16 + lr) * ROWB + koff;
                ldm_x4(aBase + roff, af[mf]);
            }
#pragma unroll
            for (int reg = 0; reg < 4; reg++) {
                const uint32_t roff = (uint32_t)(wn * 64 + reg * 16 + lr) * ROWB + koff;
                uint32_t bh[4];
                ldm_x4(bBase + roff, bh);
#pragma unroll
                for (int mf = 0; mf < 2; mf++) {
                    mma_fp16(acc[mf][reg * 2 + 0], af[mf], bh[0], bh[2]);
                    mma_fp16(acc[mf][reg * 2 + 1], af[mf], bh[1], bh[3]);
                }
            }
        }
        __syncthreads();
    }

    const int lr4 = lid >> 2;
    const int lc2 = (lid & 3) * 2;
#pragma unroll
    for (int mf = 0; mf < 2; mf++) {
#pragma unroll
        for (int nf = 0; nf < 8; nf++) {
            const int m = mb * 128 + wm * 32 + mf * 16 + lr4;
            const int n = nb * 128 + wn * 64 + nf * 8 + lc2;
            if (n >= N) continue;
            float b0 = 0.f, b1 = 0.f;
            if (bias) { b0 = bias[n]; b1 = bias[n + 1]; }
            if (m < M) {
                float2 v = make_float2(acc[mf][nf][0] + b0, acc[mf][nf][1] + b1);
                *reinterpret_cast<float2*>(C + (long long)m * ldc + n) = v;
            }
            if (m + 8 < M) {
                float2 v = make_float2(acc[mf][nf][2] + b0, acc[mf][nf][3] + b1);
                *reinterpret_cast<float2*>(C + (long long)(m + 8) * ldc + n) = v;
            }
        }
    }
}

// =================== persistent recurrence kernel v5 (R14, 256 thr) =========
#define RNN_CTAS 128
#define RNN_THR 256
#define WT16 16384
#define HT32 32768
#define OFF_W 0
#define OFF_H0 (6 * WT16)
#define OFF_H1 (OFF_H0 + 2 * HT32)
#define OFF_P (OFF_H1 + 2 * HT32)         // 229376: P prefetch, 32x16 fp32
#define RNN_SMEM (OFF_P + 2048)           // 231424
#define OFF_R OFF_H0
#define REDSTR 17

__global__ __launch_bounds__(RNN_THR, 1)
void rnn_persist(const int* __restrict__ inputs,
                 const float* __restrict__ W0,
                 const float* __restrict__ b0,
                 const float* __restrict__ Wl,
                 const float* __restrict__ bl,
                 float* __restrict__ hfin) {
    extern __shared__ char smc[];
    const uint32_t sbase = smem_u32(smc);
    float* const smf = reinterpret_cast<float*>(smc);
    const int tid = threadIdx.x;
    const int wid = tid >> 5, lid = tid & 31;
    const int bg = blockIdx.x >> 5;
    const int cg = blockIdx.x & 31;
    const int cbase = cg * 16;

    for (int i = tid; i < 16 * 512; i += RNN_THR) {
        const int r = i >> 9, k = i & 511;
        const int gc = cbase + r;
        const uint32_t off = r * 1024 + (((k >> 3) ^ (r & 7)) << 4) + (k & 7) * 2;
        float v[3];
        v[0] = W0[gc * 1024 + k];
        v[1] = Wl[gc * 1024 + 512 + k];
        v[2] = Wl[gc * 1024 + k];
#pragma unroll
        for (int t = 0; t < 3; t++) {
            const __nv_bfloat16 hi = __float2bfloat16(v[t]);
            const __nv_bfloat16 lo = __float2bfloat16(v[t] - __bfloat162float(hi));
            char* base = smc + OFF_W + (2 * t) * WT16 + off;
            *reinterpret_cast<__nv_bfloat16*>(base) = hi;
            *reinterpret_cast<__nv_bfloat16*>(base + WT16) = lo;
        }
    }
    __syncthreads();

    const int mw = wid & 1;
    const int kw = wid >> 1;
    const int lr = lid & 15, lc = lid >> 4;

    const int ecoll = tid & 15, erow = tid >> 4;
    const int ecol = cbase + ecoll;
    const float b0c = b0[ecol], blc = bl[ecol];

    const int arow = mw * 16 + lr;
    const uint32_t aRowH0 = sbase + OFF_H0 + arow * 1024;
    const uint32_t aRowH1 = sbase + OFF_H1 + arow * 1024;
    const uint32_t bRow = sbase + OFF_W + lr * 1024;
    const int axor = arow & 7;
    const int bxor = lr & 7;
    const int c0 = kw * 16 + lc;

    unsigned int* const gbar = &g_sync4[bg * 32];

    auto stage_h = [&](uint32_t offBase, const __nv_bfloat16* hi,
                       const __nv_bfloat16* lo) {
#pragma unroll
        for (int j = 0; j < 16; j++) {
            const int idx = tid + j * 256;
            const int tile = idx >> 11;
            const int c = idx & 2047;
            const int row = c >> 6, ch = c & 63;
            const __nv_bfloat16* src =
                (tile ? lo : hi) + (long long)(bg * 32 + row) * HH + ch * 8;
            const uint32_t dst = sbase + offBase + tile * HT32 + row * 1024 +
                                 ((ch ^ (row & 7)) << 4);
            asm volatile("cp.async.cg.shared.global [%0], [%1], 16;"
                         :: "r"(dst), "l"(src) : "memory");
        }
        asm volatile("cp.async.commit_group;" ::: "memory");
    };

    for (int p = 0; p <= SS; p++) {
        float acc0[2][4] = {{0, 0, 0, 0}, {0, 0, 0, 0}};
        float acc1[2][4] = {{0, 0, 0, 0}, {0, 0, 0, 0}};

        if (p < SS && tid < 128) {
            const int row = tid >> 2, ch = tid & 3;
            const int tok = __ldg(inputs + p * BB + bg * 32 + row);
            const float* src = g_P + (long long)tok * HH + cbase + ch * 4;
            const uint32_t dst = sbase + OFF_P + row * 64 + ch * 16;
            asm volatile("cp.async.cg.shared.global [%0], [%1], 16;"
                         :: "r"(dst), "l"(src) : "memory");
        }
        stage_h(OFF_H0, g_h0bh[(p + 1) & 1], g_h0bl[(p + 1) & 1]);
        stage_h(OFF_H1, g_h1bh[p & 1], g_h1bl[p & 1]);
        asm volatile("cp.async.wait_group 1;" ::: "memory");   // P+h0 ready
        __syncthreads();

        // ---- pass A: h0 x W0h -> acc0 ; h0 x Wlx -> acc1 ----
#pragma unroll
        for (int i = 0; i < 8; i++) {
            const uint32_t sc = (uint32_t)((c0 + i * 2) ^ axor) << 4;
            const uint32_t wc = (uint32_t)((c0 + i * 2) ^ bxor) << 4;
            uint32_t ah[4], al[4], b0h[4], b0l[4], bxh[4], bxl[4];
            ldm_x4(aRowH0 + sc, ah);
            ldm_x4(aRowH0 + HT32 + sc, al);
            ldm_x4(bRow + 0 * WT16 + wc, b0h);
            ldm_x4(bRow + 1 * WT16 + wc, b0l);
            ldm_x4(bRow + 2 * WT16 + wc, bxh);
            ldm_x4(bRow + 3 * WT16 + wc, bxl);
            mma_bf16(acc0[0], ah, b0h[0], b0h[2]);
            mma_bf16(acc0[1], ah, b0h[1], b0h[3]);
            mma_bf16(acc0[0], ah, b0l[0], b0l[2]);
            mma_bf16(acc0[1], ah, b0l[1], b0l[3]);
            mma_bf16(acc0[0], al, b0h[0], b0h[2]);
            mma_bf16(acc0[1], al, b0h[1], b0h[3]);
            mma_bf16(acc1[0], ah, bxh[0], bxh[2]);
            mma_bf16(acc1[1], ah, bxh[1], bxh[3]);
            mma_bf16(acc1[0], ah, bxl[0], bxl[2]);
            mma_bf16(acc1[1], ah, bxl[1], bxl[3]);
            mma_bf16(acc1[0], al, bxh[0], bxh[2]);
            mma_bf16(acc1[1], al, bxh[1], bxh[3]);
        }

        asm volatile("cp.async.wait_group 0;" ::: "memory");   // h1 ready
        __syncthreads();

        // ---- pass B: h1 x Wlh -> acc1 ----
#pragma unroll
        for (int i = 0; i < 8; i++) {
            const uint32_t sc = (uint32_t)((c0 + i * 2) ^ axor) << 4;
            const uint32_t wc = (uint32_t)((c0 + i * 2) ^ bxor) << 4;
            uint32_t ah[4], al[4], bhh[4], bhl[4];
            ldm_x4(aRowH1 + sc, ah);
            ldm_x4(aRowH1 + HT32 + sc, al);
            ldm_x4(bRow + 4 * WT16 + wc, bhh);
            ldm_x4(bRow + 5 * WT16 + wc, bhl);
            mma_bf16(acc1[0], ah, bhh[0], bhh[2]);
            mma_bf16(acc1[1], ah, bhh[1], bhh[3]);
            mma_bf16(acc1[0], ah, bhl[0], bhl[2]);
            mma_bf16(acc1[1], ah, bhl[1], bhl[3]);
            mma_bf16(acc1[0], al, bhh[0], bhh[2]);
            mma_bf16(acc1[1], al, bhh[1], bhh[3]);
        }

        // ---- write k-slice frags to red (aliases h0 buffer) ----
        {
            const int rg = lid >> 2, cc = (lid & 3) * 2;
            float* red = smf + OFF_R / 4;
            const int m = mw * 16 + rg;
#pragma unroll
            for (int nf = 0; nf < 2; nf++) {
                const int n = nf * 8 + cc;
                float* r0 = red + ((0 * 4 + kw) * 32 + m) * REDSTR + n;
                float* r1 = red + ((1 * 4 + kw) * 32 + m) * REDSTR + n;
                r0[0] = acc0[nf][0]; r0[1] = acc0[nf][1];
                r0[8 * REDSTR] = acc0[nf][2]; r0[8 * REDSTR + 1] = acc0[nf][3];
                r1[0] = acc1[nf][0]; r1[1] = acc1[nf][1];
                r1[8 * REDSTR] = acc1[nf][2]; r1[8 * REDSTR + 1] = acc1[nf][3];
            }
        }
        __syncthreads();

        // ---- epilogue ----
        __half t16s[2];
        {
            float* red = smf + OFF_R / 4;
            const float* smP = smf + OFF_P / 4;
#pragma unroll
            for (int e = 0; e < 2; e++) {
                const int row = erow + e * 16;
                const int gbr = bg * 32 + row;
                float s0 = 0.f, s1 = 0.f;
#pragma unroll
                for (int q = 0; q < 4; q++) {
                    s0 += red[((0 * 4 + q) * 32 + row) * REDSTR + ecoll];
                    s1 += red[((1 * 4 + q) * 32 + row) * REDSTR + ecoll];
                }
                const long long o = (long long)gbr * HH + ecol;
                if (p < SS) {
                    const float v = tanhf(s0 + smP[row * 16 + ecoll] + b0c);
                    const __nv_bfloat16 hv = __float2bfloat16(v);
                    const __nv_bfloat16 lv = __float2bfloat16(v - __bfloat162float(hv));
                    g_h0bh[p & 1][o] = hv;
                    g_h0bl[p & 1][o] = lv;
                    if (p == SS - 1) hfin[o] = v;
                }
                if (p >= 1) {
                    const float v = tanhf(s1 + blc);
                    const __nv_bfloat16 hv = __float2bfloat16(v);
                    const __nv_bfloat16 lv = __float2bfloat16(v - __bfloat162float(hv));
                    g_h1bh[(p + 1) & 1][o] = hv;
                    g_h1bl[(p + 1) & 1][o] = lv;
                    t16s[e] = __float2half(v);
                    if (p == SS) hfin[BB * HH + o] = v;
                }
            }
        }

        if (p < SS) {
            __syncthreads();
            if (tid == 0) {
                asm volatile("red.release.gpu.global.add.u32 [%0], 1;"
                             :: "l"(gbar) : "memory");
            }
        }

        if (p >= 1) {
            const int s = p - 1;
#pragma unroll
            for (int e = 0; e < 2; e++) {
                const int gbr = bg * 32 + erow + e * 16;
                const long long ot = ((long long)s * BB + gbr) * HH + ecol;
                g_T16[ot] = t16s[e];
            }
        }

        if (p < SS) {
            if (tid == 0) {
                const unsigned int target = (unsigned)(p + 1) * 32;
                unsigned int v;
                do {
                    asm volatile("ld.acquire.gpu.global.u32 %0, [%1];"
                                 : "=r"(v) : "l"(gbar) : "memory");
                } while (v < target);
            }
            __syncthreads();
        }
    }
}

// ---------------- fused prep kernel ------------------------------------------
// One launch covers: emb fp16 split (VV*EE), Wout fp16 conv (VV*HH),
// W0x fp16 (HH*EE), hidden-state init (BB*HH), barrier counters (128).
__global__ void prep_all(const float* __restrict__ emb,
                         const float* __restrict__ Wout,
                         const float* __restrict__ W0,
                         const float* __restrict__ hidden,
                         float scale) {
    const int i = blockIdx.x * blockDim.x + threadIdx.x;
    if (i < VV * EE) {
        float v = emb[i] * scale;
        __half h = __float2half(v);
        g_E16h[i] = h;
        g_E16l[i] = __float2half(v - __half2float(h));
    }
    if (i < VV * HH) {
        g_W16[i] = __float2half(Wout[i]);
    }
    if (i < HH * EE) {
        const int c = i / EE, e = i % EE;
        g_X16[i] = __float2half(W0[c * (HH + EE) + HH + e]);
    }
    if (i < BB * HH) {
        float v0 = hidden[i];
        __nv_bfloat16 h0 = __float2bfloat16(v0);
        g_h0bh[1][i] = h0;
        g_h0bl[1][i] = __float2bfloat16(v0 - __bfloat162float(h0));
        float v1 = hidden[BB * HH + i];
        __nv_bfloat16 h1 = __float2bfloat16(v1);
        g_h1bh[1][i] = h1;
        g_h1bl[1][i] = __float2bfloat16(v1 - __bfloat162float(h1));
    }
    if (i < 128) g_sync4[i] = 0;
}

// ---------------- launch ------------------------------------------------------
extern "C" void kernel_launch(void* const* d_in, const int* in_sizes, int n_in,
                              void* d_out, int out_size) {
    const int*   inputs = (const int*)  d_in[0];
    const float* hidden = (const float*)d_in[1];
    const float* emb    = (const float*)d_in[2];
    const float* W0     = (const float*)d_in[3];
    const float* b0     = (const float*)d_in[4];
    const float* Wl     = (const float*)d_in[5];
    const float* bl     = (const float*)d_in[6];
    const float* Wout   = (const float*)d_in[7];
    const float* bout   = (const float*)d_in[8];

    float* logits = (float*)d_out;
    float* hfin   = (float*)d_out + (long long)SS * BB * VV;

    cudaFuncSetAttribute(gemm_fp16, cudaFuncAttributeMaxDynamicSharedMemorySize,
                         F16_SMEM);
    cudaFuncSetAttribute(gemm_f16_1p, cudaFuncAttributeMaxDynamicSharedMemorySize,
                         F161_SMEM);
    cudaFuncSetAttribute(rnn_persist, cudaFuncAttributeMaxDynamicSharedMemorySize,
                         RNN_SMEM);

    float* pP = nullptr;
    cudaGetSymbolAddress((void**)&pP, g_P);
    __half *pT16, *pW16, *pEh, *pEl, *pX16;
    cudaGetSymbolAddress((void**)&pT16, g_T16);
    cudaGetSymbolAddress((void**)&pW16, g_W16);
    cudaGetSymbolAddress((void**)&pEh, g_E16h);
    cudaGetSymbolAddress((void**)&pEl, g_E16l);
    cudaGetSymbolAddress((void**)&pX16, g_X16);

    const float scale = 22.62741699796952f;  // sqrt(512)

    // 1. fused prep (one launch)
    prep_all<<<(VV * EE + 255) / 256, 256>>>(emb, Wout, W0, hidden, scale);

    // 2. P = scale*emb @ W0x^T  (fp16 2-pass)
    {
        dim3 grid((HH + 127) / 128, (VV + 127) / 128);
        gemm_fp16<<<grid, 256, F16_SMEM>>>(pEh, pEl, pX16,
                                           VV, HH, pP, HH, nullptr);
    }

    // 3. recurrence (256-thread persistent kernel, R14 configuration)
    rnn_persist<<<RNN_CTAS, RNN_THR, RNN_SMEM>>>(inputs, W0, b0, Wl, bl, hfin);

    // 4. logits = tops @ Wout^T + bout  (fp16 single-pass)
    {
        dim3 grid((VV + 127) / 128, (SS * BB + 127) / 128);
        gemm_f16_1p<<<grid, 256, F161_SMEM>>>(pT16, pW16,
                                              SS * BB, VV, logits, VV, bout);
    }
}